// round 8
// baseline (speedup 1.0000x reference)
#include <cuda_runtime.h>
#include <cstdint>

// ===========================================================================
// NNUE eval via tensor-core mma.sync (tf32, m16n8k8), compute_103-safe PTX.
// 296 persistent CTAs x 256 threads; tile = 128 samples; warp owns 16 rows.
// ~97.5 KB smem/CTA -> 2 CTAs/SM (16 warps, occ 25%).
// ===========================================================================

__device__ __forceinline__ uint32_t f2tf32(float f) {
    uint32_t r; asm("cvt.rna.tf32.f32 %0, %1;" : "=r"(r) : "f"(f)); return r;
}

__device__ __forceinline__ void mma8(float* d,
                                     uint32_t a0, uint32_t a1, uint32_t a2, uint32_t a3,
                                     uint32_t b0, uint32_t b1) {
    asm volatile(
        "mma.sync.aligned.m16n8k8.row.col.f32.tf32.tf32.f32 "
        "{%0,%1,%2,%3}, {%4,%5,%6,%7}, {%8,%9}, {%0,%1,%2,%3};"
        : "+f"(d[0]), "+f"(d[1]), "+f"(d[2]), "+f"(d[3])
        : "r"(a0), "r"(a1), "r"(a2), "r"(a3), "r"(b0), "r"(b1));
}

// ---- pre-packed per-lane B fragments (device globals) ---------------------
__device__ uint32_t g_Bf1[13 * 8 * 32 * 2];
__device__ uint32_t g_Bf2[8 * 4 * 32 * 2];
__device__ uint32_t g_Bf3[4 * 4 * 32 * 2];

__global__ void nnue_setup(const float* __restrict__ Ww,
                           const float* __restrict__ Wb,
                           const float* __restrict__ W0,
                           const float* __restrict__ W1) {
    int t = blockIdx.x * blockDim.x + threadIdx.x;
    if (t < 6656) {
        int e = t & 1, lane = (t >> 1) & 31, tn = (t >> 6) & 7, s = t >> 9;
        int n = 8 * tn + (lane >> 2);
        int k = 8 * s + (lane & 3) + 4 * e;
        float v = 0.0f;
        if (k < 98) {
            if (n < 32) v = Ww[n * 98 + k];
            else { int kk = k + 49; if (kk >= 98) kk -= 98; v = Wb[(n - 32) * 98 + kk]; }
        }
        g_Bf1[t] = f2tf32(v);
    }
    if (t < 2048) {
        int e = t & 1, lane = (t >> 1) & 31, tn = (t >> 6) & 3, s = t >> 8;
        int n = 8 * tn + (lane >> 2);
        int k = 8 * s + (lane & 3) + 4 * e;
        g_Bf2[t] = f2tf32(W0[n * 64 + k]);
    }
    if (t < 1024) {
        int e = t & 1, lane = (t >> 1) & 31, tn = (t >> 6) & 3, s = t >> 8;
        int n = 8 * tn + (lane >> 2);
        int k = 8 * s + (lane & 3) + 4 * e;
        g_Bf3[t] = f2tf32(W1[n * 32 + k]);
    }
}

// ---- smem layout (u32 offsets) --------------------------------------------
// XP raw: 128 rows x stride 104 (pair layout).  base overlays at stride 72
// (exactly [0,9216)); x0 at [9216,14336) stride 40 (aliases raw rows 89..127,
// ordered by the post-layer-1 block sync).  Strides ≡ 8 (mod 32): conflict-
// free LDS.64 A-fragment loads.
#define U_XP    0
#define U_X0    9216
#define U_BF1   14336
#define U_BF2   20992
#define U_BF3   23040
#define U_BIAS1 24064
#define U_B0    24128
#define U_B1    24160
#define U_W2    24192
#define U_POV   24256
#define U_B2    24384
#define SMEM_BYTES (24388 * 4)

// swizzled column offset within a pair-layout row (col 0..103)
__device__ __forceinline__ int coff(int col) {
    return (col & 0xF8) | ((col & 3) << 1) | ((col >> 2) & 1);
}

__global__ __launch_bounds__(256, 2)
void nnue_mma(const float* __restrict__ pov,
              const float* __restrict__ white,
              const float* __restrict__ black,
              const float* __restrict__ bw,
              const float* __restrict__ bb,
              const float* __restrict__ b0,
              const float* __restrict__ b1,
              const float* __restrict__ W2,
              const float* __restrict__ b2,
              float* __restrict__ out, int ntiles) {
    extern __shared__ __align__(16) uint32_t shu[];
    float* shf = (float*)shu;
    const int t = threadIdx.x;
    const int lane = t & 31, wid = t >> 5;
    const int g = lane >> 2, q = lane & 3;
    const int r0 = wid * 16;

    // ---- one-time: fragments + vectors ------------------------------------
    {
        uint4* d = (uint4*)(shu + U_BF1); const uint4* s = (const uint4*)g_Bf1;
        for (int i = t; i < 1664; i += 256) d[i] = s[i];
        d = (uint4*)(shu + U_BF2); s = (const uint4*)g_Bf2;
        for (int i = t; i < 512; i += 256) d[i] = s[i];
        d = (uint4*)(shu + U_BF3); s = (const uint4*)g_Bf3;
        for (int i = t; i < 256; i += 256) d[i] = s[i];
    }
    if (t < 64) shf[U_BIAS1 + t] = (t < 32) ? bw[t] : bb[t - 32];
    if (t < 64) shf[U_W2 + t]    = W2[t];
    if (t < 32) shf[U_B0 + t]    = b0[t];
    if (t < 32) shf[U_B1 + t]    = b1[t];
    if (t == 0) shf[U_B2]        = b2[0];
    __syncthreads();
    const float b2val = shf[U_B2];

    // staging decomposition of i = t; each +256 step: k += 11, s += 5 (mod 49)
    const int s_init = t / 49;
    const int k_init = t - s_init * 49;

    for (int tile = blockIdx.x; tile < ntiles; tile += gridDim.x) {
        const size_t s0 = (size_t)tile * 128;

        // ---- stage X (tf32, pair layout) + pov ----------------------------
        {
            const float* wp = white + s0 * 49;
            const float* bp = black + s0 * 49;
            int s = s_init, k = k_init;
#pragma unroll 1
            for (int j = 0; j < 25; j++) {
                int i = t + (j << 8);
                if (i < 128 * 49) {
                    float wv = wp[i];
                    float bv = bp[i];
                    int base = s * 104;
                    shu[U_XP + base + coff(k)]      = f2tf32(wv);
                    shu[U_XP + base + coff(k + 49)] = f2tf32(bv);
                }
                k += 11; s += 5;
                if (k >= 49) { k -= 49; s += 1; }
            }
        }
        {   // zero pad cols 98..103 (128*6 = 768 slots)
            for (int i = t; i < 768; i += 256) {
                int s = i / 6;
                int c = 98 + (i - s * 6);
                shu[U_XP + s * 104 + coff(c)] = 0;
            }
        }
        if (t < 128) shf[U_POV + t] = pov[s0 + t];
        __syncthreads();

        // ---- layer 1: D1[128x64] = X @ Wc^T, K=104 ------------------------
        float acc1[8][4];
#pragma unroll
        for (int tn = 0; tn < 8; tn++)
#pragma unroll
            for (int r = 0; r < 4; r++) acc1[tn][r] = 0.0f;

#pragma unroll
        for (int s = 0; s < 13; s++) {
            uint2 aa[2];
#pragma unroll
            for (int h = 0; h < 2; h++)
                aa[h] = *(const uint2*)&shu[U_XP + (r0 + 8 * h + g) * 104 + (s * 4 + q) * 2];
#pragma unroll
            for (int tn = 0; tn < 8; tn++) {
                uint2 bv = *(const uint2*)&shu[U_BF1 + ((s * 8 + tn) * 32 + lane) * 2];
                mma8(acc1[tn], aa[0].x, aa[1].x, aa[0].y, aa[1].y, bv.x, bv.y);
            }
        }
        __syncthreads();   // all raw-XP reads complete before base/x0 overlay

        // ---- epilogue 1: bias + pov mix + relu -> base (stride 72) --------
#pragma unroll
        for (int h = 0; h < 2; h++) {
            int row = r0 + 8 * h + g;
            float p  = shf[U_POV + row];
            float q1 = 1.0f - p;
#pragma unroll
            for (int tn = 0; tn < 4; tn++)
#pragma unroll
                for (int c = 0; c < 2; c++) {
                    int col = 8 * tn + 2 * q + c;
                    float lo = acc1[tn][2 * h + c]     + shf[U_BIAS1 + col];
                    float hi = acc1[tn + 4][2 * h + c] + shf[U_BIAS1 + 32 + col];
                    float v0 = fmaxf(p * lo + q1 * hi, 0.0f);
                    float v1 = fmaxf(p * hi + q1 * lo, 0.0f);
                    shu[U_XP + row * 72 + coff(col)]      = f2tf32(v0);
                    shu[U_XP + row * 72 + coff(col + 32)] = f2tf32(v1);
                }
        }
        __syncwarp();

        // ---- layer 2: D2[128x32] = base @ W0^T, K=64 ----------------------
        float acc2[4][4];
#pragma unroll
        for (int tn = 0; tn < 4; tn++)
#pragma unroll
            for (int r = 0; r < 4; r++) acc2[tn][r] = 0.0f;

#pragma unroll
        for (int s = 0; s < 8; s++) {
            uint2 aa[2];
#pragma unroll
            for (int h = 0; h < 2; h++)
                aa[h] = *(const uint2*)&shu[U_XP + (r0 + 8 * h + g) * 72 + (s * 4 + q) * 2];
#pragma unroll
            for (int tn = 0; tn < 4; tn++) {
                uint2 bv = *(const uint2*)&shu[U_BF2 + ((s * 4 + tn) * 32 + lane) * 2];
                mma8(acc2[tn], aa[0].x, aa[1].x, aa[0].y, aa[1].y, bv.x, bv.y);
            }
        }

        // ---- epilogue 2: x0 = relu(D2+b0) -> X0 (stride 40); W2[0:32] dot -
        float dot[2] = {0.0f, 0.0f};
#pragma unroll
        for (int h = 0; h < 2; h++) {
            int row = r0 + 8 * h + g;
#pragma unroll
            for (int tn = 0; tn < 4; tn++)
#pragma unroll
                for (int c = 0; c < 2; c++) {
                    int col = 8 * tn + 2 * q + c;
                    float v = fmaxf(acc2[tn][2 * h + c] + shf[U_B0 + col], 0.0f);
                    dot[h] += v * shf[U_W2 + col];
                    int r8 = col & 7;
                    shu[U_X0 + row * 40 + (tn * 4 + (r8 & 3)) * 2 + (r8 >> 2)] = f2tf32(v);
                }
        }
        __syncwarp();

        // ---- layer 3: D3[128x32] = x0 @ W1^T, K=32 ------------------------
        float acc3[4][4];
#pragma unroll
        for (int tn = 0; tn < 4; tn++)
#pragma unroll
            for (int r = 0; r < 4; r++) acc3[tn][r] = 0.0f;

#pragma unroll
        for (int s = 0; s < 4; s++) {
            uint2 aa[2];
#pragma unroll
            for (int h = 0; h < 2; h++)
                aa[h] = *(const uint2*)&shu[U_X0 + (r0 + 8 * h + g) * 40 + (s * 4 + q) * 2];
#pragma unroll
            for (int tn = 0; tn < 4; tn++) {
                uint2 bv = *(const uint2*)&shu[U_BF3 + ((s * 4 + tn) * 32 + lane) * 2];
                mma8(acc3[tn], aa[0].x, aa[1].x, aa[0].y, aa[1].y, bv.x, bv.y);
            }
        }

        // ---- epilogue 3: dot += relu(D3+b1).W2[32:]; reduce; store --------
#pragma unroll
        for (int h = 0; h < 2; h++) {
#pragma unroll
            for (int tn = 0; tn < 4; tn++)
#pragma unroll
                for (int c = 0; c < 2; c++) {
                    int col = 8 * tn + 2 * q + c;
                    float v = fmaxf(acc3[tn][2 * h + c] + shf[U_B1 + col], 0.0f);
                    dot[h] += v * shf[U_W2 + 32 + col];
                }
            float d = dot[h];
            d += __shfl_xor_sync(0xffffffffu, d, 1);
            d += __shfl_xor_sync(0xffffffffu, d, 2);
            if (q == 0)
                out[s0 + r0 + 8 * h + g] = d + b2val;
        }
        __syncthreads();   // XP/base/x0 free before next tile's staging
    }
}

// ---------------------------------------------------------------------------
extern "C" void kernel_launch(void* const* d_in, const int* in_sizes, int n_in,
                              void* d_out, int out_size) {
    const float* pov   = (const float*)d_in[0];
    const float* white = (const float*)d_in[1];
    const float* black = (const float*)d_in[2];
    const float* Ww    = (const float*)d_in[3];
    const float* bw    = (const float*)d_in[4];
    const float* Wb    = (const float*)d_in[5];
    const float* bb    = (const float*)d_in[6];
    const float* W0    = (const float*)d_in[7];
    const float* b0    = (const float*)d_in[8];
    const float* W1    = (const float*)d_in[9];
    const float* b1    = (const float*)d_in[10];
    const float* W2    = (const float*)d_in[11];
    const float* b2    = (const float*)d_in[12];

    const int B = in_sizes[0];
    const int ntiles = B / 128;

    cudaFuncSetAttribute(nnue_mma,
                         cudaFuncAttributeMaxDynamicSharedMemorySize, SMEM_BYTES);

    nnue_setup<<<26, 256>>>(Ww, Wb, W0, W1);
    nnue_mma<<<296, 256, SMEM_BYTES>>>(pov, white, black, bw, bb,
                                       b0, b1, W2, b2, (float*)d_out, ntiles);
}